// round 3
// baseline (speedup 1.0000x reference)
#include <cuda_runtime.h>
#include <cstdint>

// Problem shape (fixed)
#define B_  32
#define L_  512
#define D_  768
#define H_  100
#define C_  45
#define M_  (B_ * L_)          // 16384 rows
#define NPAD 48                // padded cols
#define WSTR 772               // wS col stride (c-major), floats (768 + 4 pad)
#define BM 64                  // rows per GEMM block
#define BK 64                  // k chunk
#define ALD 68                 // aS row stride (floats)
#define NCHUNK (D_ / BK)       // 12
#define GTHREADS 512
#define PTHREADS 512

// Device scratch (no allocation allowed)
__device__ float g_WcT[NPAD * WSTR];   // fused weight, c-major [c][d] padded
__device__ float g_cvec[NPAD];         // W2@b1 + b2
__device__ int   g_gather[M_];         // compacted source index or -1

// fma on packed f32x2 (FFMA2)
#define FMA2(d, a, b) asm("fma.rn.f32x2 %0, %1, %2, %3;" : "=l"(d) : "l"(a), "l"(b), "l"(d))

// ---------------------------------------------------------------------------
// Prep: blocks 0..31 -> compaction (ballot scan), blocks 32..103 -> weight fuse
// ---------------------------------------------------------------------------
__global__ void __launch_bounds__(PTHREADS)
prep_kernel(const int* __restrict__ valid_ids,
            const float* __restrict__ W1,
            const float* __restrict__ b1,
            const float* __restrict__ W2,
            const float* __restrict__ b2) {
    const int t = threadIdx.x;
    if (blockIdx.x < B_) {
        // ---- compaction for batch b ----
        __shared__ int wsum[16];
        const int b = blockIdx.x;
        const int v = (valid_ids[b * L_ + t] == 1);
        const unsigned mask = __ballot_sync(0xffffffffu, v);
        const int lane = t & 31, wid = t >> 5;
        const int wprefix = __popc(mask & ((1u << lane) - 1u));
        if (lane == 0) wsum[wid] = __popc(mask);
        g_gather[b * L_ + t] = -1;
        __syncthreads();
        if (t < 16) {
            int x = wsum[t];
#pragma unroll
            for (int off = 1; off < 16; off <<= 1) {
                int y = __shfl_up_sync(0xffffu, x, off);
                if (t >= off) x += y;
            }
            wsum[t] = x;
        }
        __syncthreads();
        const int base = (wid == 0) ? 0 : wsum[wid - 1];
        if (v) g_gather[b * L_ + base + wprefix] = t;
    } else {
        // ---- weight fuse: WcT[c][d] = sum_h W2[c][h] * W1[h][d] ----
        const int gidx = (blockIdx.x - B_) * PTHREADS + t;   // 0..36863
        const int c = gidx / D_;
        const int d = gidx - c * D_;
        float s = 0.0f;
        if (c < C_) {
#pragma unroll 4
            for (int h = 0; h < H_; h++)
                s += W2[c * H_ + h] * W1[h * D_ + d];
        }
        g_WcT[c * WSTR + d] = s;
        if (blockIdx.x == B_ && t < NPAD) {
            float cv = 0.0f;
            if (t < C_) {
                for (int h = 0; h < H_; h++) cv += W2[t * H_ + h] * b1[h];
                cv += b2[t];
            }
            g_cvec[t] = cv;
        }
    }
}

// ---------------------------------------------------------------------------
// GEMM: out[row][c] = sum_d x[b][gather[row]][d] * Wc[c][d] + cvec[c]
// 256 blocks x 512 threads, 64 rows each. Per-thread: 2 rows x 3 cols.
// Warp = 8-ty x 4-tx patch -> dedup both a (broadcast x4) and w (broadcast x8).
// ---------------------------------------------------------------------------
#define SMEM_W  (NPAD * WSTR)            // 37056 floats
#define SMEM_A  (2 * BM * ALD)           // 8704 floats (double buffered)
#define SMEM_FLOATS (SMEM_W + SMEM_A + NPAD)
#define SMEM_BYTES (SMEM_FLOATS * 4 + BM * 4)

extern "C" __global__ void __launch_bounds__(GTHREADS, 1)
gemm_kernel(const float* __restrict__ x, float* __restrict__ out) {
    extern __shared__ float smem[];
    float* wS = smem;                    // [48][772] c-major
    float* aS = smem + SMEM_W;           // 2 x [64][68]
    float* cS = aS + SMEM_A;             // [48]
    int*   gS = (int*)(cS + NPAD);       // [64]

    const int tid  = threadIdx.x;
    const int row0 = blockIdx.x * BM;

    if (tid < BM)   gS[tid] = g_gather[row0 + tid];
    if (tid < NPAD) cS[tid] = g_cvec[tid];
    __syncthreads();

    // Fully-invalid block: output is the constant vector.
    if (gS[0] < 0) {
        float* o = out + (size_t)row0 * C_;
        for (int i = tid; i < BM * C_; i += GTHREADS)
            o[i] = cS[i % C_];
        return;
    }

    const int b = row0 / L_;
    const float* xb = x + (size_t)b * L_ * D_;

    // A staging: thread stages rows {tid>>4, tid>>4 + 32}, quad q = tid&15
    const int qr = tid >> 4;             // 0..31
    const int q  = tid & 15;             // float4 index within 64-k row
    const float* xrow[2];
    {
        const int s0 = gS[qr];
        const int s1 = gS[qr + 32];
        xrow[0] = (s0 >= 0) ? (xb + (size_t)s0 * D_) : nullptr;
        xrow[1] = (s1 >= 0) ? (xb + (size_t)s1 * D_) : nullptr;
    }

    // Prefetch A chunk 0 first (long-latency LDG)
    float4 pf[2];
#pragma unroll
    for (int j = 0; j < 2; j++)
        pf[j] = xrow[j] ? *(const float4*)(xrow[j] + q * 4)
                        : make_float4(0.f, 0.f, 0.f, 0.f);

    // Stage full Wc (identical padded layout in global & smem: linear copy)
    {
        const float4* s4 = (const float4*)g_WcT;
        float4* d4 = (float4*)wS;
        for (int i = tid; i < SMEM_W / 4; i += GTHREADS) d4[i] = s4[i];
    }
    // Store A chunk 0
    *(float4*)(aS + qr * ALD + q * 4)        = pf[0];
    *(float4*)(aS + (qr + 32) * ALD + q * 4) = pf[1];
    __syncthreads();

    // Compute-thread mapping: warp covers 8-ty x 4-tx patch
    const int lane = tid & 31;
    const int w    = tid >> 5;                   // 0..15
    const int ty   = (w & 3) * 8 + (lane & 7);   // 0..31 -> rows ty, ty+32
    const int tx   = (w >> 2) * 4 + (lane >> 3); // 0..15 -> cols 3tx..3tx+2

    unsigned long long acc[2][3];
#pragma unroll
    for (int r = 0; r < 2; r++)
#pragma unroll
        for (int c = 0; c < 3; c++) acc[r][c] = 0ull;

    const float* w0b = wS + (3 * tx + 0) * WSTR;
    const float* w1b = wS + (3 * tx + 1) * WSTR;
    const float* w2b = wS + (3 * tx + 2) * WSTR;

    for (int ch = 0; ch < NCHUNK; ch++) {
        // Prefetch next A chunk
        if (ch < NCHUNK - 1) {
            const int k0n = (ch + 1) * BK;
#pragma unroll
            for (int j = 0; j < 2; j++)
                pf[j] = xrow[j] ? *(const float4*)(xrow[j] + k0n + q * 4)
                                : make_float4(0.f, 0.f, 0.f, 0.f);
        }

        const float* ab0 = aS + (ch & 1) * BM * ALD + ty * ALD;
        const float* ab1 = ab0 + 32 * ALD;
        const float* wc0 = w0b + ch * BK;
        const float* wc1 = w1b + ch * BK;
        const float* wc2 = w2b + ch * BK;

#pragma unroll
        for (int s = 0; s < BK / 4; s++) {     // 16 steps of 4 k each
            const ulonglong2 a0 = *(const ulonglong2*)(ab0 + 4 * s);
            const ulonglong2 a1 = *(const ulonglong2*)(ab1 + 4 * s);
            const ulonglong2 w0 = *(const ulonglong2*)(wc0 + 4 * s);
            const ulonglong2 w1 = *(const ulonglong2*)(wc1 + 4 * s);
            const ulonglong2 w2 = *(const ulonglong2*)(wc2 + 4 * s);

            FMA2(acc[0][0], a0.x, w0.x); FMA2(acc[0][0], a0.y, w0.y);
            FMA2(acc[0][1], a0.x, w1.x); FMA2(acc[0][1], a0.y, w1.y);
            FMA2(acc[0][2], a0.x, w2.x); FMA2(acc[0][2], a0.y, w2.y);
            FMA2(acc[1][0], a1.x, w0.x); FMA2(acc[1][0], a1.y, w0.y);
            FMA2(acc[1][1], a1.x, w1.x); FMA2(acc[1][1], a1.y, w1.y);
            FMA2(acc[1][2], a1.x, w2.x); FMA2(acc[1][2], a1.y, w2.y);
        }

        if (ch < NCHUNK - 1) {
            float* nb = aS + ((ch + 1) & 1) * BM * ALD;
            *(float4*)(nb + qr * ALD + q * 4)        = pf[0];
            *(float4*)(nb + (qr + 32) * ALD + q * 4) = pf[1];
            __syncthreads();
        }
    }

    // Epilogue: reduce f32x2 halves, add cvec, store cols < 45
    const int cb = 3 * tx;
    if (cb < C_) {
#pragma unroll
        for (int r = 0; r < 2; r++) {
            const int row = row0 + ty + 32 * r;
            float* o = out + (size_t)row * C_;
#pragma unroll
            for (int c = 0; c < 3; c++) {
                if (cb + c < C_) {
                    const unsigned long long v = acc[r][c];
                    const float lo = __uint_as_float((unsigned)(v & 0xffffffffu));
                    const float hi = __uint_as_float((unsigned)(v >> 32));
                    o[cb + c] = lo + hi + cS[cb + c];
                }
            }
        }
    }
}

// ---------------------------------------------------------------------------
extern "C" void kernel_launch(void* const* d_in, const int* in_sizes, int n_in,
                              void* d_out, int out_size) {
    const float* x   = (const float*)d_in[0];   // (32,512,768) f32
    const int*   vid = (const int*)  d_in[1];   // (32,512) i32
    const float* W1  = (const float*)d_in[2];   // (100,768)
    const float* b1  = (const float*)d_in[3];   // (100,)
    const float* W2  = (const float*)d_in[4];   // (45,100)
    const float* b2  = (const float*)d_in[5];   // (45,)
    float* out = (float*)d_out;                 // (16384,45)

    static bool attr_set = false;
    if (!attr_set) {
        cudaFuncSetAttribute(gemm_kernel,
                             cudaFuncAttributeMaxDynamicSharedMemorySize,
                             SMEM_BYTES);
        attr_set = true;
    }

    prep_kernel<<<B_ + (NPAD * D_) / PTHREADS, PTHREADS>>>(vid, W1, b1, W2, b2);
    gemm_kernel<<<M_ / BM, GTHREADS, SMEM_BYTES>>>(x, out);
}

// round 6
// speedup vs baseline: 1.2962x; 1.2962x over previous
#include <cuda_runtime.h>
#include <cuda_bf16.h>
#include <cstdint>

// Problem shape (fixed)
#define B_  32
#define L_  512
#define D_  768
#define H_  100
#define C_  45
#define M_  (B_ * L_)           // 16384 rows
#define NB  48                  // padded N
#define BM  64                  // rows per CTA -> 256 CTAs
#define NCHUNK 12               // 12 chunks of 64 f32 k
#define GT  256
#define PT  512

#define ABYT 8192               // A tile bytes per term (64 rows * 128B)
#define BBYT 6144               // B tile bytes per term (48 rows * 128B)
#define BUFSZ (2*ABYT + 2*BBYT) // 28672 per stage
#define OFF_CVEC (2*BUFSZ)      // 57344
#define OFF_GS   (OFF_CVEC + 192)
#define SMEM_USE (OFF_GS + 256)
#define SMEM_BYTES (SMEM_USE + 1024)

#define SW(o) ((o) ^ (((o) >> 3) & 0x70))

// Device scratch. g_Wb: Wc split hi/lo bf16, SW128 pre-swizzled,
// layout [chunk][term hi/lo][48 rows][128B].
__device__ unsigned char g_Wb[NCHUNK * 2 * BBYT];
__device__ float g_cvec[NB];
__device__ int   g_gather[M_];

// ---------------------------------------------------------------------------
// PTX helpers (arch-portable: ldmatrix sm_75+, mma.bf16 sm_80+)
// ---------------------------------------------------------------------------
__device__ __forceinline__ uint32_t smem_u32(const void* p) {
    uint32_t a;
    asm("{ .reg .u64 t; cvta.to.shared.u64 t, %1; cvt.u32.u64 %0, t; }"
        : "=r"(a) : "l"(p));
    return a;
}
__device__ __forceinline__ uint32_t bf2(float lo, float hi) {
    uint32_t r;   // packed bf16x2: low half = lo, high half = hi
    asm("cvt.rn.bf16x2.f32 %0, %1, %2;" : "=r"(r) : "f"(hi), "f"(lo));
    return r;
}
__device__ __forceinline__ void ldsm4(uint32_t* r, uint32_t a) {
    asm volatile("ldmatrix.sync.aligned.m8n8.x4.shared.b16 {%0,%1,%2,%3}, [%4];"
                 : "=r"(r[0]), "=r"(r[1]), "=r"(r[2]), "=r"(r[3]) : "r"(a));
}
__device__ __forceinline__ void ldsm2(uint32_t* r, uint32_t a) {
    asm volatile("ldmatrix.sync.aligned.m8n8.x2.shared.b16 {%0,%1}, [%2];"
                 : "=r"(r[0]), "=r"(r[1]) : "r"(a));
}
__device__ __forceinline__ void mma_bf16(float* c, const uint32_t* a,
                                         uint32_t b0, uint32_t b1) {
    asm volatile(
        "mma.sync.aligned.m16n8k16.row.col.f32.bf16.bf16.f32 "
        "{%0,%1,%2,%3}, {%4,%5,%6,%7}, {%8,%9}, {%0,%1,%2,%3};"
        : "+f"(c[0]), "+f"(c[1]), "+f"(c[2]), "+f"(c[3])
        : "r"(a[0]), "r"(a[1]), "r"(a[2]), "r"(a[3]), "r"(b0), "r"(b1));
}

// ---------------------------------------------------------------------------
// Prep: blocks 0..31 -> compaction; blocks 32..103 -> weight fuse + bf16 split
// ---------------------------------------------------------------------------
__global__ void __launch_bounds__(PT)
prep_kernel(const int* __restrict__ valid_ids,
            const float* __restrict__ W1,
            const float* __restrict__ b1,
            const float* __restrict__ W2,
            const float* __restrict__ b2) {
    const int t = threadIdx.x;
    if (blockIdx.x < B_) {
        __shared__ int wsum[16];
        const int b = blockIdx.x;
        const int v = (valid_ids[b * L_ + t] == 1);
        const unsigned mask = __ballot_sync(0xffffffffu, v);
        const int lane = t & 31, wid = t >> 5;
        const int wprefix = __popc(mask & ((1u << lane) - 1u));
        if (lane == 0) wsum[wid] = __popc(mask);
        g_gather[b * L_ + t] = -1;
        __syncthreads();
        if (t < 16) {
            int x = wsum[t];
#pragma unroll
            for (int off = 1; off < 16; off <<= 1) {
                int y = __shfl_up_sync(0xffffu, x, off);
                if (t >= off) x += y;
            }
            wsum[t] = x;
        }
        __syncthreads();
        const int base = (wid == 0) ? 0 : wsum[wid - 1];
        if (v) g_gather[b * L_ + base + wprefix] = t;
    } else {
        const int gidx = (blockIdx.x - B_) * PT + t;   // 0..36863
        const int c = gidx / D_;
        const int d = gidx - c * D_;
        float s = 0.0f;
        if (c < C_) {
#pragma unroll 4
            for (int h = 0; h < H_; h++)
                s += W2[c * H_ + h] * W1[h * D_ + d];
        }
        __nv_bfloat16 hb = __float2bfloat16(s);
        __nv_bfloat16 lb = __float2bfloat16(s - __bfloat162float(hb));
        const int ch = d >> 6;
        const uint32_t off = (uint32_t)c * 128 + (uint32_t)(d & 63) * 2;
        const uint32_t sw = SW(off);
        *(__nv_bfloat16*)(g_Wb + ch * 2 * BBYT + sw)        = hb;
        *(__nv_bfloat16*)(g_Wb + ch * 2 * BBYT + BBYT + sw) = lb;

        if (blockIdx.x == B_ && t < NB) {
            float cv = 0.0f;
            if (t < C_) {
                for (int h = 0; h < H_; h++) cv += W2[t * H_ + h] * b1[h];
                cv += b2[t];
            }
            g_cvec[t] = cv;
        }
    }
}

// ---------------------------------------------------------------------------
// GEMM via mma.sync bf16 3-term split. CTA = 64 rows x 48 cols, 8 warps.
// Warp (rw = w&3, cw = w>>2): 16 rows x 24 cols (3 n8 tiles).
// Swizzle discipline: per-thread XOR mask from row bits, applied to the FULL
// byte offset at every use (column deltas never cross the 128B row).
// ---------------------------------------------------------------------------
extern "C" __global__ void __launch_bounds__(GT, 2)
gemm_kernel(const float* __restrict__ x, float* __restrict__ out) {
    extern __shared__ unsigned char smem_raw[];
    const uint32_t sb_raw = smem_u32(smem_raw);
    const uint32_t pad = (1024u - (sb_raw & 1023u)) & 1023u;
    unsigned char* sm = smem_raw + pad;
    const uint32_t sb = sb_raw + pad;

    float* cS = (float*)(sm + OFF_CVEC);
    int*   gS = (int*)(sm + OFF_GS);

    const int tid  = threadIdx.x;
    const int row0 = blockIdx.x * BM;

    if (tid < BM) gS[tid] = g_gather[row0 + tid];
    if (tid < NB) cS[tid] = g_cvec[tid];
    __syncthreads();

    // Fully-invalid block: constant rows.
    if (gS[0] < 0) {
        float* o = out + (size_t)row0 * C_;
        for (int i = tid; i < BM * C_; i += GT)
            o[i] = cS[i % C_];
        return;
    }

    // Producer mapping: thread -> A row tid>>2, f32 cols [16q, 16q+16)
    const int r = tid >> 2;
    const int q = tid & 3;
    const int src = gS[r];
    const int b = row0 / L_;
    const float* xr = (src >= 0)
        ? (x + ((size_t)b * L_ + src) * D_ + q * 16) : nullptr;

    // Compute mapping
    const int lane = tid & 31;
    const int w    = tid >> 5;
    const int rw   = w & 3;      // row group: rows 16rw..16rw+15
    const int cw   = w >> 2;     // col group: cols 24cw..24cw+23

    // Pre-swizzle offsets + per-thread XOR masks (row bits constant per thread)
    const uint32_t aoff = (uint32_t)(rw * 16 + (lane & 15)) * 128
                        + (uint32_t)((lane >> 4) << 4);
    const uint32_t xa   = (aoff >> 3) & 0x70;
    const int l16 = lane & 15;
    uint32_t boff[3], xb[3];
#pragma unroll
    for (int j = 0; j < 3; j++) {
        boff[j] = (uint32_t)(cw * 24 + j * 8 + (l16 & 7)) * 128
                + (uint32_t)((l16 >> 3) << 4);
        xb[j]   = (boff[j] >> 3) & 0x70;
    }

    // A STS offset + mask
    const uint32_t soff = (uint32_t)r * 128 + (uint32_t)q * 32;
    const uint32_t xs   = (soff >> 3) & 0x70;

    float4 v[4], vn[4];
#pragma unroll
    for (int j = 0; j < 4; j++)
        v[j] = xr ? *(const float4*)(xr + 4 * j) : make_float4(0.f, 0.f, 0.f, 0.f);

    float acc[3][4];
#pragma unroll
    for (int j = 0; j < 3; j++)
#pragma unroll
        for (int k = 0; k < 4; k++) acc[j][k] = 0.f;

    for (int ch = 0; ch < NCHUNK; ch++) {
        const int bsel = ch & 1;
        unsigned char* bufg = sm + bsel * BUFSZ;
        const uint32_t bufs = sb + bsel * BUFSZ;

        // Convert + store A hi/lo (SW128 swizzled, mask applied to full offset)
#pragma unroll
        for (int i = 0; i < 2; i++) {
            const float4 a = v[2 * i], c = v[2 * i + 1];
            uint4 uh, ul;
            uh.x = bf2(a.x, a.y); uh.y = bf2(a.z, a.w);
            uh.z = bf2(c.x, c.y); uh.w = bf2(c.z, c.w);
            ul.x = bf2(a.x - __uint_as_float(uh.x << 16),
                       a.y - __uint_as_float(uh.x & 0xffff0000u));
            ul.y = bf2(a.z - __uint_as_float(uh.y << 16),
                       a.w - __uint_as_float(uh.y & 0xffff0000u));
            ul.z = bf2(c.x - __uint_as_float(uh.z << 16),
                       c.y - __uint_as_float(uh.z & 0xffff0000u));
            ul.w = bf2(c.z - __uint_as_float(uh.w << 16),
                       c.w - __uint_as_float(uh.w & 0xffff0000u));
            const uint32_t sw = (soff + 16u * i) ^ xs;
            *(uint4*)(bufg + sw)        = uh;
            *(uint4*)(bufg + ABYT + sw) = ul;
        }

        // Copy B hi+lo chunk (pre-swizzled): 12288 B = 768 float4
        {
            const float4* bs = (const float4*)(g_Wb + ch * 2 * BBYT);
            float4* bd = (float4*)(bufg + 2 * ABYT);
#pragma unroll
            for (int idx = 0; idx < 3; idx++)
                bd[tid + idx * GT] = bs[tid + idx * GT];
        }
        __syncthreads();

        // Prefetch next chunk's A (after sync so LDG overlaps MMA)
        if (ch < NCHUNK - 1) {
#pragma unroll
            for (int j = 0; j < 4; j++)
                vn[j] = xr ? *(const float4*)(xr + (ch + 1) * 64 + 4 * j)
                           : make_float4(0.f, 0.f, 0.f, 0.f);
        }

        // Consume: 4 k16 steps x 3 n-tiles x 3 terms
        const uint32_t aB = bufs, bB = bufs + 2 * ABYT;
#pragma unroll
        for (int s = 0; s < 4; s++) {
            const uint32_t ad = (aoff + 32u * s) ^ xa;
            uint32_t ah[4], al[4];
            ldsm4(ah, aB + ad);
            ldsm4(al, aB + ABYT + ad);
#pragma unroll
            for (int j = 0; j < 3; j++) {
                const uint32_t bd_ = (boff[j] + 32u * s) ^ xb[j];
                uint32_t bh[2], bl[2];
                ldsm2(bh, bB + bd_);
                ldsm2(bl, bB + BBYT + bd_);
                mma_bf16(acc[j], ah, bh[0], bh[1]);
                mma_bf16(acc[j], ah, bl[0], bl[1]);
                mma_bf16(acc[j], al, bh[0], bh[1]);
            }
        }
        __syncthreads();

#pragma unroll
        for (int j = 0; j < 4; j++) v[j] = vn[j];
    }

    // Epilogue: D frag -> global. row = 16rw + lane>>2 (+8), col = 24cw+8j+2(lane&3)
    const int rbase = row0 + rw * 16 + (lane >> 2);
#pragma unroll
    for (int j = 0; j < 3; j++) {
        const int cb = cw * 24 + j * 8 + (lane & 3) * 2;
        const float c0 = cS[cb], c1 = cS[cb + 1];
#pragma unroll
        for (int h = 0; h < 2; h++) {
            float* o = out + (size_t)(rbase + 8 * h) * C_;
            if (cb < C_)     o[cb]     = acc[j][2 * h]     + c0;
            if (cb + 1 < C_) o[cb + 1] = acc[j][2 * h + 1] + c1;
        }
    }
}

// ---------------------------------------------------------------------------
extern "C" void kernel_launch(void* const* d_in, const int* in_sizes, int n_in,
                              void* d_out, int out_size) {
    const float* x   = (const float*)d_in[0];   // (32,512,768) f32
    const int*   vid = (const int*)  d_in[1];   // (32,512) i32
    const float* W1  = (const float*)d_in[2];   // (100,768)
    const float* b1  = (const float*)d_in[3];   // (100,)
    const float* W2  = (const float*)d_in[4];   // (45,100)
    const float* b2  = (const float*)d_in[5];   // (45,)
    float* out = (float*)d_out;                 // (16384,45)

    static bool attr_set = false;
    if (!attr_set) {
        cudaFuncSetAttribute(gemm_kernel,
                             cudaFuncAttributeMaxDynamicSharedMemorySize,
                             SMEM_BYTES);
        attr_set = true;
    }

    prep_kernel<<<B_ + (NB * D_) / PT, PT>>>(vid, W1, b1, W2, b2);
    gemm_kernel<<<M_ / BM, GT, SMEM_BYTES>>>(x, out);
}

// round 7
// speedup vs baseline: 1.4783x; 1.1405x over previous
#include <cuda_runtime.h>
#include <cuda_bf16.h>
#include <cstdint>

// Problem shape (fixed)
#define B_  32
#define L_  512
#define D_  768
#define H_  100
#define C_  45
#define M_  (B_ * L_)           // 16384 rows
#define NB  48                  // padded N
#define BM  64                  // rows per CTA -> 256 CTAs
#define NCHUNK 12               // 12 chunks of 64 f32 k
#define GT  256
#define PT  512

#define ABYT 8192               // A tile bytes per term (64 rows * 128B)
#define BBYT 6144               // B tile bytes per term (48 rows * 128B)
#define BUFSZ (2*ABYT + 2*BBYT) // 28672 per stage
#define OFF_CVEC (2*BUFSZ)      // 57344
#define OFF_GS   (OFF_CVEC + 192)
#define SMEM_USE (OFF_GS + 256)
#define SMEM_BYTES (SMEM_USE + 1024)

#define SW(o) ((o) ^ (((o) >> 3) & 0x70))

// Device scratch. g_Wb: Wc split hi/lo bf16, SW128 pre-swizzled,
// layout [chunk][term hi/lo][48 rows][128B].
__device__ unsigned char g_Wb[NCHUNK * 2 * BBYT];
__device__ float g_cvec[NB];
__device__ int   g_gather[M_];

// ---------------------------------------------------------------------------
// PTX helpers (arch-portable: ldmatrix sm_75+, mma.bf16 sm_80+, cp.async sm_80+)
// ---------------------------------------------------------------------------
__device__ __forceinline__ uint32_t smem_u32(const void* p) {
    uint32_t a;
    asm("{ .reg .u64 t; cvta.to.shared.u64 t, %1; cvt.u32.u64 %0, t; }"
        : "=r"(a) : "l"(p));
    return a;
}
__device__ __forceinline__ uint32_t bf2(float lo, float hi) {
    uint32_t r;   // packed bf16x2: low half = lo, high half = hi
    asm("cvt.rn.bf16x2.f32 %0, %1, %2;" : "=r"(r) : "f"(hi), "f"(lo));
    return r;
}
__device__ __forceinline__ void ldsm4(uint32_t* r, uint32_t a) {
    asm volatile("ldmatrix.sync.aligned.m8n8.x4.shared.b16 {%0,%1,%2,%3}, [%4];"
                 : "=r"(r[0]), "=r"(r[1]), "=r"(r[2]), "=r"(r[3]) : "r"(a));
}
__device__ __forceinline__ void ldsm2(uint32_t* r, uint32_t a) {
    asm volatile("ldmatrix.sync.aligned.m8n8.x2.shared.b16 {%0,%1}, [%2];"
                 : "=r"(r[0]), "=r"(r[1]) : "r"(a));
}
__device__ __forceinline__ void mma_bf16(float* c, const uint32_t* a,
                                         uint32_t b0, uint32_t b1) {
    asm volatile(
        "mma.sync.aligned.m16n8k16.row.col.f32.bf16.bf16.f32 "
        "{%0,%1,%2,%3}, {%4,%5,%6,%7}, {%8,%9}, {%0,%1,%2,%3};"
        : "+f"(c[0]), "+f"(c[1]), "+f"(c[2]), "+f"(c[3])
        : "r"(a[0]), "r"(a[1]), "r"(a[2]), "r"(a[3]), "r"(b0), "r"(b1));
}
__device__ __forceinline__ void cpasync16(uint32_t dst, const void* src) {
    asm volatile("cp.async.cg.shared.global [%0], [%1], 16;"
                 :: "r"(dst), "l"(src) : "memory");
}
__device__ __forceinline__ void cp_commit() {
    asm volatile("cp.async.commit_group;" ::: "memory");
}
__device__ __forceinline__ void cp_wait0() {
    asm volatile("cp.async.wait_group 0;" ::: "memory");
}

// ---------------------------------------------------------------------------
// Prep: blocks 0..31 -> compaction; blocks 32..103 -> weight fuse + bf16 split
// ---------------------------------------------------------------------------
__global__ void __launch_bounds__(PT)
prep_kernel(const int* __restrict__ valid_ids,
            const float* __restrict__ W1,
            const float* __restrict__ b1,
            const float* __restrict__ W2,
            const float* __restrict__ b2) {
    const int t = threadIdx.x;
    if (blockIdx.x < B_) {
        __shared__ int wsum[16];
        const int b = blockIdx.x;
        const int v = (valid_ids[b * L_ + t] == 1);
        const unsigned mask = __ballot_sync(0xffffffffu, v);
        const int lane = t & 31, wid = t >> 5;
        const int wprefix = __popc(mask & ((1u << lane) - 1u));
        if (lane == 0) wsum[wid] = __popc(mask);
        g_gather[b * L_ + t] = -1;
        __syncthreads();
        if (t < 16) {
            int x = wsum[t];
#pragma unroll
            for (int off = 1; off < 16; off <<= 1) {
                int y = __shfl_up_sync(0xffffu, x, off);
                if (t >= off) x += y;
            }
            wsum[t] = x;
        }
        __syncthreads();
        const int base = (wid == 0) ? 0 : wsum[wid - 1];
        if (v) g_gather[b * L_ + base + wprefix] = t;
    } else {
        const int gidx = (blockIdx.x - B_) * PT + t;   // 0..36863
        const int c = gidx / D_;
        const int d = gidx - c * D_;
        float s0 = 0.f, s1 = 0.f, s2 = 0.f, s3 = 0.f;
        if (c < C_) {
#pragma unroll
            for (int h = 0; h < H_; h += 4) {
                s0 += W2[c * H_ + h + 0] * W1[(h + 0) * D_ + d];
                s1 += W2[c * H_ + h + 1] * W1[(h + 1) * D_ + d];
                s2 += W2[c * H_ + h + 2] * W1[(h + 2) * D_ + d];
                s3 += W2[c * H_ + h + 3] * W1[(h + 3) * D_ + d];
            }
        }
        const float s = (s0 + s1) + (s2 + s3);
        __nv_bfloat16 hb = __float2bfloat16(s);
        __nv_bfloat16 lb = __float2bfloat16(s - __bfloat162float(hb));
        const int ch = d >> 6;
        const uint32_t off = (uint32_t)c * 128 + (uint32_t)(d & 63) * 2;
        const uint32_t sw = SW(off);
        *(__nv_bfloat16*)(g_Wb + ch * 2 * BBYT + sw)        = hb;
        *(__nv_bfloat16*)(g_Wb + ch * 2 * BBYT + BBYT + sw) = lb;

        if (blockIdx.x == B_ && t < NB) {
            float cv = 0.0f;
            if (t < C_) {
                for (int h = 0; h < H_; h++) cv += W2[t * H_ + h] * b1[h];
                cv += b2[t];
            }
            g_cvec[t] = cv;
        }
    }
}

// ---------------------------------------------------------------------------
// GEMM via mma.sync bf16 3-term split. CTA = 64 rows x 48 cols, 8 warps.
// Pipeline per chunk: LDG prefetch -> convert/STS A -> cp.async.wait ->
// sync -> issue cp.async B(next) -> consume (ldmatrix + MMA).
// One barrier per chunk; B arrives via cp.async; A prefetch covered by
// convert + barrier + MMA section.
// ---------------------------------------------------------------------------
extern "C" __global__ void __launch_bounds__(GT, 3)
gemm_kernel(const float* __restrict__ x, float* __restrict__ out) {
    extern __shared__ unsigned char smem_raw[];
    const uint32_t sb_raw = smem_u32(smem_raw);
    const uint32_t pad = (1024u - (sb_raw & 1023u)) & 1023u;
    unsigned char* sm = smem_raw + pad;
    const uint32_t sb = sb_raw + pad;

    float* cS = (float*)(sm + OFF_CVEC);
    int*   gS = (int*)(sm + OFF_GS);

    const int tid  = threadIdx.x;
    const int row0 = blockIdx.x * BM;

    if (tid < BM) gS[tid] = g_gather[row0 + tid];
    if (tid < NB) cS[tid] = g_cvec[tid];
    __syncthreads();

    // Fully-invalid block: constant rows.
    if (gS[0] < 0) {
        float* o = out + (size_t)row0 * C_;
        for (int i = tid; i < BM * C_; i += GT)
            o[i] = cS[i % C_];
        return;
    }

    // Producer mapping: thread -> A row tid>>2, f32 cols [16q, 16q+16)
    const int r = tid >> 2;
    const int q = tid & 3;
    const int src = gS[r];
    const int b = row0 / L_;
    const float* xr = (src >= 0)
        ? (x + ((size_t)b * L_ + src) * D_ + q * 16) : nullptr;

    // Compute mapping
    const int lane = tid & 31;
    const int w    = tid >> 5;
    const int rw   = w & 3;      // row group: rows 16rw..16rw+15
    const int cw   = w >> 2;     // col group: cols 24cw..24cw+23

    // ldmatrix offsets + per-thread XOR masks (applied to FULL offset each use)
    const uint32_t aoff = (uint32_t)(rw * 16 + (lane & 15)) * 128
                        + (uint32_t)((lane >> 4) << 4);
    const uint32_t xa   = (aoff >> 3) & 0x70;
    const int l16 = lane & 15;
    uint32_t boff[3], xb[3];
#pragma unroll
    for (int j = 0; j < 3; j++) {
        boff[j] = (uint32_t)(cw * 24 + j * 8 + (l16 & 7)) * 128
                + (uint32_t)((l16 >> 3) << 4);
        xb[j]   = (boff[j] >> 3) & 0x70;
    }

    // A STS offset + mask
    const uint32_t soff = (uint32_t)r * 128 + (uint32_t)q * 32;
    const uint32_t xs   = (soff >> 3) & 0x70;

    // Pre-loop: cp.async B chunk 0 into stage 0; LDG A chunk 0.
    {
        const unsigned char* bs = g_Wb;
        const uint32_t bd = sb + 2 * ABYT;   // stage 0 B region
#pragma unroll
        for (int idx = 0; idx < 3; idx++)
            cpasync16(bd + (tid + idx * GT) * 16, bs + (tid + idx * GT) * 16);
        cp_commit();
    }

    float4 v[4], vn[4];
#pragma unroll
    for (int j = 0; j < 4; j++)
        v[j] = xr ? *(const float4*)(xr + 4 * j) : make_float4(0.f, 0.f, 0.f, 0.f);

    float acc[3][4];
#pragma unroll
    for (int j = 0; j < 3; j++)
#pragma unroll
        for (int k = 0; k < 4; k++) acc[j][k] = 0.f;

    for (int ch = 0; ch < NCHUNK; ch++) {
        const int bsel = ch & 1;
        unsigned char* bufg = sm + bsel * BUFSZ;
        const uint32_t bufs = sb + bsel * BUFSZ;

        // Prefetch next chunk's A (independent regs; covered by convert+sync+MMA)
        if (ch < NCHUNK - 1) {
#pragma unroll
            for (int j = 0; j < 4; j++)
                vn[j] = xr ? *(const float4*)(xr + (ch + 1) * 64 + 4 * j)
                           : make_float4(0.f, 0.f, 0.f, 0.f);
        }

        // Convert + store A hi/lo (SW128 swizzled)
#pragma unroll
        for (int i = 0; i < 2; i++) {
            const float4 a = v[2 * i], c = v[2 * i + 1];
            uint4 uh, ul;
            uh.x = bf2(a.x, a.y); uh.y = bf2(a.z, a.w);
            uh.z = bf2(c.x, c.y); uh.w = bf2(c.z, c.w);
            ul.x = bf2(a.x - __uint_as_float(uh.x << 16),
                       a.y - __uint_as_float(uh.x & 0xffff0000u));
            ul.y = bf2(a.z - __uint_as_float(uh.y << 16),
                       a.w - __uint_as_float(uh.y & 0xffff0000u));
            ul.z = bf2(c.x - __uint_as_float(uh.z << 16),
                       c.y - __uint_as_float(uh.z & 0xffff0000u));
            ul.w = bf2(c.z - __uint_as_float(uh.w << 16),
                       c.w - __uint_as_float(uh.w & 0xffff0000u));
            const uint32_t sw = (soff + 16u * i) ^ xs;
            *(uint4*)(bufg + sw)        = uh;
            *(uint4*)(bufg + ABYT + sw) = ul;
        }

        // B(ch) cp.async must be complete before the barrier publishes it.
        cp_wait0();
        __syncthreads();

        // Issue cp.async for B(ch+1) into the other stage (lands during MMA).
        if (ch < NCHUNK - 1) {
            const unsigned char* bs = g_Wb + (ch + 1) * 2 * BBYT;
            const uint32_t bd = sb + ((ch + 1) & 1) * BUFSZ + 2 * ABYT;
#pragma unroll
            for (int idx = 0; idx < 3; idx++)
                cpasync16(bd + (tid + idx * GT) * 16, bs + (tid + idx * GT) * 16);
            cp_commit();
        }

        // Consume: 4 k16 steps x 3 n-tiles x 3 terms
        const uint32_t aB = bufs, bB = bufs + 2 * ABYT;
#pragma unroll
        for (int s = 0; s < 4; s++) {
            const uint32_t ad = (aoff + 32u * s) ^ xa;
            uint32_t ah[4], al[4];
            ldsm4(ah, aB + ad);
            ldsm4(al, aB + ABYT + ad);
#pragma unroll
            for (int j = 0; j < 3; j++) {
                const uint32_t bd_ = (boff[j] + 32u * s) ^ xb[j];
                uint32_t bh[2], bl[2];
                ldsm2(bh, bB + bd_);
                ldsm2(bl, bB + BBYT + bd_);
                mma_bf16(acc[j], ah, bh[0], bh[1]);
                mma_bf16(acc[j], ah, bl[0], bl[1]);
                mma_bf16(acc[j], al, bh[0], bh[1]);
            }
        }

#pragma unroll
        for (int j = 0; j < 4; j++) v[j] = vn[j];
    }

    // Epilogue: D frag -> global. row = 16rw + lane>>2 (+8), col = 24cw+8j+2(lane&3)
    const int rbase = row0 + rw * 16 + (lane >> 2);
#pragma unroll
    for (int j = 0; j < 3; j++) {
        const int cb = cw * 24 + j * 8 + (lane & 3) * 2;
        const float c0 = cS[cb], c1 = cS[cb + 1];
#pragma unroll
        for (int h = 0; h < 2; h++) {
            float* o = out + (size_t)(rbase + 8 * h) * C_;
            if (cb < C_)     o[cb]     = acc[j][2 * h]     + c0;
            if (cb + 1 < C_) o[cb + 1] = acc[j][2 * h + 1] + c1;
        }
    }
}

// ---------------------------------------------------------------------------
extern "C" void kernel_launch(void* const* d_in, const int* in_sizes, int n_in,
                              void* d_out, int out_size) {
    const float* x   = (const float*)d_in[0];   // (32,512,768) f32
    const int*   vid = (const int*)  d_in[1];   // (32,512) i32
    const float* W1  = (const float*)d_in[2];   // (100,768)
    const float* b1  = (const float*)d_in[3];   // (100,)
    const float* W2  = (const float*)d_in[4];   // (45,100)
    const float* b2  = (const float*)d_in[5];   // (45,)
    float* out = (float*)d_out;                 // (16384,45)

    static bool attr_set = false;
    if (!attr_set) {
        cudaFuncSetAttribute(gemm_kernel,
                             cudaFuncAttributeMaxDynamicSharedMemorySize,
                             SMEM_BYTES);
        attr_set = true;
    }

    prep_kernel<<<B_ + (NB * D_) / PT, PT>>>(vid, W1, b1, W2, b2);
    gemm_kernel<<<M_ / BM, GT, SMEM_BYTES>>>(x, out);
}